// round 11
// baseline (speedup 1.0000x reference)
#include <cuda_runtime.h>
#include <stdint.h>

// Fused projection + greedy per-pixel NMS. Output dtype is FLOAT32.
//   coords_grid: [N, M, 3, H, W] f32,  anchor_P: [N, 3, 4] f32
//   out: [N, H, W, 8] f32 (indices as floats)
//
// R11: occupancy push. 2.03 thread-waves at 4 blocks/SM made makespan ~3 CTA
// rounds (huge idle tail). Block-uniform n (HW % 256 == 0 fast path) lets
// ptxas promote camera-matrix addressing to uniform regs; launch_bounds
// (256,5) pins the 5-blocks/SM class (48 regs) -> 1.62 waves.
#define TOPK 8

__device__ __forceinline__ float fast_rcp(float z) {
    float r;
    asm("rcp.approx.ftz.f32 %0, %1;" : "=f"(r) : "f"(z));
    return r;
}

// One candidate step (depth-2 pipelined). Uses/updates ambient locals.
#define CAND_BODY(MVAL)                                                       \
  do {                                                                        \
    const float* q = pf < lastp ? pf : lastp;                                 \
    const float nx = q[0];                                                    \
    const float ny = q[plane];                                                \
    const float nz = q[2 * plane];                                            \
    const float X0 = fmaf(p00, cx0, fmaf(p01, cy0, fmaf(p02, cz0, p03)));     \
    const float X1 = fmaf(p10, cx0, fmaf(p11, cy0, fmaf(p12, cz0, p13)));     \
    const float X2 = fmaf(p20, cx0, fmaf(p21, cy0, fmaf(p22, cz0, p23)));     \
    const float zc = fmaxf(X2, 1e-6f);                                        \
    const float iv = fast_rcp(zc);                                            \
    const float x  = X0 * iv;                                                 \
    const float y  = X1 * iv;                                                 \
    float d2_[TOPK];                                                          \
    _Pragma("unroll")                                                         \
    for (int k = 0; k < TOPK; k++) {                                          \
      const float dx = sx[k] - x;                                             \
      const float dy = sy[k] - y;                                             \
      d2_[k] = fmaf(dx, dx, dy * dy);                                         \
    }                                                                         \
    const float dmn = fminf(fminf(fminf(d2_[0], d2_[1]), fminf(d2_[2], d2_[3])), \
                            fminf(fminf(d2_[4], d2_[5]), fminf(d2_[6], d2_[7]))); \
    if ((dmn > 4.0f) && (cnt < TOPK)) {                                       \
      _Pragma("unroll")                                                       \
      for (int k = 1; k < TOPK; k++) {                                        \
        if (cnt == k) { sx[k] = x; sy[k] = y; }                               \
      }                                                                       \
      si64 |= (uint64_t)(uint32_t)(MVAL) << (cnt * 8);                        \
      cnt++;                                                                  \
    }                                                                         \
    cx0 = cx1; cy0 = cy1; cz0 = cz1;                                          \
    cx1 = nx;  cy1 = ny;  cz1 = nz;                                           \
    pf += mstride;                                                            \
  } while (0)

// Fast path: requires HW % 256 == 0 (every CTA within one image n),
// 2 <= M <= 255, grid covers total exactly.
template <bool VEC_STORE>
__global__ __launch_bounds__(256, 5)
void nms_coords_kernel(const float* __restrict__ coords,
                       const float* __restrict__ P,
                       float* __restrict__ out,
                       int HW, int M)
{
    // Block-uniform image index -> ptxas promotes to uniform registers.
    const int bpix = blockIdx.x * 256;
    const int n    = bpix / HW;                  // uniform across the CTA
    const int pix  = bpix - n * HW + threadIdx.x;

    const float* Pn = P + n * 12;
    const float p00 = Pn[0], p01 = Pn[1], p02 = Pn[2],  p03 = Pn[3];
    const float p10 = Pn[4], p11 = Pn[5], p12 = Pn[6],  p13 = Pn[7];
    const float p20 = Pn[8], p21 = Pn[9], p22 = Pn[10], p23 = Pn[11];

    const long long plane   = HW;
    const long long mstride = 3 * plane;
    const float* base  = coords + (long long)n * M * mstride + pix;
    const float* lastp = base + (long long)(M - 1) * mstride;

    float sx[TOPK], sy[TOPK];
#pragma unroll
    for (int k = 0; k < TOPK; k++) { sx[k] = 1e9f; sy[k] = 1e9f; }
    uint64_t si64 = 0;                    // 8 kept indices, byte-packed (M<256)

    // Peel m = 0: always kept (sentinel slots, cnt==0); index byte stays 0.
    {
        const float cx = base[0];
        const float cy = base[plane];
        const float cz = base[2 * plane];
        const float X0 = fmaf(p00, cx, fmaf(p01, cy, fmaf(p02, cz, p03)));
        const float X1 = fmaf(p10, cx, fmaf(p11, cy, fmaf(p12, cz, p13)));
        const float X2 = fmaf(p20, cx, fmaf(p21, cy, fmaf(p22, cz, p23)));
        const float zc = fmaxf(X2, 1e-6f);
        const float iv = fast_rcp(zc);
        sx[0] = X0 * iv; sy[0] = X1 * iv;
    }
    int cnt = 1;

    // Depth-2 pipeline prime.
    const float* s1 = (base + mstride)     < lastp ? (base + mstride)     : lastp;
    const float* s2 = (base + 2 * mstride) < lastp ? (base + 2 * mstride) : lastp;
    float cx0 = s1[0], cy0 = s1[plane], cz0 = s1[2 * plane];
    float cx1 = s2[0], cy1 = s2[plane], cz1 = s2[2 * plane];
    const float* pf = base + 3 * mstride;

    // Vote-free warm-up: cnt cannot reach 8 before m = 7.
    int m = 1;
    const int mchk = (M < TOPK) ? M : TOPK;
    for (; m < mchk; m++) { CAND_BODY(m); }
    // Checked region: early-exit once every lane has kept 8.
    for (; m < M; m++) {
        CAND_BODY(m);
        if (__all_sync(0xffffffffu, cnt >= TOPK)) break;
    }

    // Unpack byte-packed indices to floats.
    const uint32_t lo = (uint32_t)si64;
    const uint32_t hi = (uint32_t)(si64 >> 32);
    const float f0 = (float)( lo        & 0xff);
    const float f1 = (float)((lo >>  8) & 0xff);
    const float f2 = (float)((lo >> 16) & 0xff);
    const float f3 = (float)((lo >> 24)       );
    const float f4 = (float)( hi        & 0xff);
    const float f5 = (float)((hi >>  8) & 0xff);
    const float f6 = (float)((hi >> 16) & 0xff);
    const float f7 = (float)((hi >> 24)       );

    const long long tid = (long long)bpix + threadIdx.x + (long long)n * 0; // = global pixel
    const long long opix = (long long)n * HW + pix;
    (void)tid;
    if (VEC_STORE) {
        float4* o = reinterpret_cast<float4*>(out) + opix * 2;
        o[0] = make_float4(f0, f1, f2, f3);
        o[1] = make_float4(f4, f5, f6, f7);
    } else {
        float* o = out + opix * TOPK;
        o[0]=f0; o[1]=f1; o[2]=f2; o[3]=f3; o[4]=f4; o[5]=f5; o[6]=f6; o[7]=f7;
    }
}

// Generic fallback (any M, any HW alignment): simple, correct.
__global__ __launch_bounds__(256)
void nms_coords_kernel_generic(const float* __restrict__ coords,
                               const float* __restrict__ P,
                               float* __restrict__ out,
                               int HW, int M, int total)
{
    const int tid = blockIdx.x * 256 + threadIdx.x;
    if (tid >= total) return;
    const int n   = tid / HW;
    const int pix = tid - n * HW;
    const float* Pn = P + n * 12;
    const float p00 = Pn[0], p01 = Pn[1], p02 = Pn[2],  p03 = Pn[3];
    const float p10 = Pn[4], p11 = Pn[5], p12 = Pn[6],  p13 = Pn[7];
    const float p20 = Pn[8], p21 = Pn[9], p22 = Pn[10], p23 = Pn[11];
    const long long plane = HW, mstride = 3 * plane;
    const float* cm = coords + (long long)n * M * mstride + pix;

    float sx[TOPK], sy[TOPK]; int si[TOPK];
#pragma unroll
    for (int k = 0; k < TOPK; k++) { sx[k] = 1e9f; sy[k] = 1e9f; si[k] = 0; }
    int cnt = 0;
    for (int m = 0; m < M; m++, cm += mstride) {
        const float cx = cm[0], cy = cm[plane], cz = cm[2 * plane];
        const float X0 = fmaf(p00, cx, fmaf(p01, cy, fmaf(p02, cz, p03)));
        const float X1 = fmaf(p10, cx, fmaf(p11, cy, fmaf(p12, cz, p13)));
        const float X2 = fmaf(p20, cx, fmaf(p21, cy, fmaf(p22, cz, p23)));
        const float zc = fmaxf(X2, 1e-6f);
        const float x = X0 / zc, y = X1 / zc;
        float dmin = 3.402823e38f;
#pragma unroll
        for (int k = 0; k < TOPK; k++) {
            const float dx = sx[k] - x, dy = sy[k] - y;
            dmin = fminf(dmin, fmaf(dx, dx, dy * dy));
        }
        if (dmin > 4.0f && cnt < TOPK) {
#pragma unroll
            for (int k = 0; k < TOPK; k++)
                if (cnt == k) { sx[k] = x; sy[k] = y; si[k] = m; }
            cnt++;
        }
    }
    float* o = out + (long long)tid * TOPK;
#pragma unroll
    for (int k = 0; k < TOPK; k++) o[k] = (float)si[k];
}

extern "C" void kernel_launch(void* const* d_in, const int* in_sizes, int n_in,
                              void* d_out, int out_size)
{
    int ci = 0, pi = 0;
    for (int i = 1; i < n_in; i++) {
        if (in_sizes[i] > in_sizes[ci]) ci = i;
        if (in_sizes[i] < in_sizes[pi]) pi = i;
    }
    const float* coords = (const float*)d_in[ci];
    const float* P      = (const float*)d_in[pi];
    float* out          = (float*)d_out;

    const long long p_elems      = in_sizes[pi];
    const long long coords_elems = in_sizes[ci];
    const int N  = (int)(p_elems / 12);
    const int HW = (int)(out_size / (TOPK * (long long)N));
    const int M  = (int)(coords_elems / (3LL * N * HW));
    const int total = N * HW;

    const bool fast = (HW % 256 == 0) && (M >= 2) && (M <= 255);
    if (fast) {
        const int blocks = total / 256;            // exact (HW % 256 == 0)
        if ((((uintptr_t)d_out) & 15u) == 0)
            nms_coords_kernel<true><<<blocks, 256>>>(coords, P, out, HW, M);
        else
            nms_coords_kernel<false><<<blocks, 256>>>(coords, P, out, HW, M);
    } else {
        const int blocks = (total + 255) / 256;
        nms_coords_kernel_generic<<<blocks, 256>>>(coords, P, out, HW, M, total);
    }
}

// round 12
// speedup vs baseline: 1.0152x; 1.0152x over previous
#include <cuda_runtime.h>
#include <stdint.h>

// Fused projection + greedy per-pixel NMS. Output dtype is FLOAT32.
//   coords_grid: [N, M, 3, H, W] f32,  anchor_P: [N, 3, 4] f32
//   out: [N, H, W, 8] f32 (indices as floats)
//
// R12: pipeline the PROJECTION one iteration ahead of the suppression test.
// proj(m+1) depends only on loaded coords, not slot state, so it overlaps
// suppress/insert(m); the MUFU rcp latency leaves the critical path.
// Loads stay at depth-2 (load at m, project at m+1, suppress at m+2).
#define TOPK 8

__device__ __forceinline__ float fast_rcp(float z) {
    float r;
    asm("rcp.approx.ftz.f32 %0, %1;" : "=f"(r) : "f"(z));
    return r;
}

#define PROJECT(cx, cy, cz, X, Y)                                             \
  do {                                                                        \
    const float X0 = fmaf(p00, (cx), fmaf(p01, (cy), fmaf(p02, (cz), p03)));  \
    const float X1 = fmaf(p10, (cx), fmaf(p11, (cy), fmaf(p12, (cz), p13)));  \
    const float X2 = fmaf(p20, (cx), fmaf(p21, (cy), fmaf(p22, (cz), p23)));  \
    const float zc = fmaxf(X2, 1e-6f);                                        \
    const float iv = fast_rcp(zc);                                            \
    (X) = X0 * iv;                                                            \
    (Y) = X1 * iv;                                                            \
  } while (0)

// One pipelined step: prefetch coords(m+2), project(m+1), suppress/insert(m).
#define CAND_BODY(MVAL)                                                       \
  do {                                                                        \
    const float* q = pf < lastp ? pf : lastp;                                 \
    const float nx = q[0];                                                    \
    const float ny = q[plane];                                                \
    const float nz = q[2 * plane];                                            \
    float x2, y2;                                                             \
    PROJECT(cx1, cy1, cz1, x2, y2);     /* projection for m+1 (indep of slots) */ \
    float d2_[TOPK];                                                          \
    _Pragma("unroll")                                                         \
    for (int k = 0; k < TOPK; k++) {                                          \
      const float dx = sx[k] - x1;                                            \
      const float dy = sy[k] - y1;                                            \
      d2_[k] = fmaf(dx, dx, dy * dy);                                         \
    }                                                                         \
    const float dmn = fminf(fminf(fminf(d2_[0], d2_[1]), fminf(d2_[2], d2_[3])), \
                            fminf(fminf(d2_[4], d2_[5]), fminf(d2_[6], d2_[7]))); \
    if ((dmn > 4.0f) && (cnt < TOPK)) {                                       \
      _Pragma("unroll")                                                       \
      for (int k = 1; k < TOPK; k++) {                                        \
        if (cnt == k) { sx[k] = x1; sy[k] = y1; }                             \
      }                                                                       \
      si64 |= (uint64_t)(uint32_t)(MVAL) << (cnt * 8);                        \
      cnt++;                                                                  \
    }                                                                         \
    x1 = x2; y1 = y2;                                                         \
    cx1 = nx; cy1 = ny; cz1 = nz;                                             \
    pf += mstride;                                                            \
  } while (0)

// Fast path: HW % 256 == 0 (CTA lies in one image), 2 <= M <= 255.
template <bool VEC_STORE>
__global__ __launch_bounds__(256, 5)
void nms_coords_kernel(const float* __restrict__ coords,
                       const float* __restrict__ P,
                       float* __restrict__ out,
                       int HW, int M)
{
    // Block-uniform image index -> uniform-register promotion.
    const int bpix = blockIdx.x * 256;
    const int n    = bpix / HW;
    const int pix  = bpix - n * HW + threadIdx.x;

    const float* Pn = P + n * 12;
    const float p00 = Pn[0], p01 = Pn[1], p02 = Pn[2],  p03 = Pn[3];
    const float p10 = Pn[4], p11 = Pn[5], p12 = Pn[6],  p13 = Pn[7];
    const float p20 = Pn[8], p21 = Pn[9], p22 = Pn[10], p23 = Pn[11];

    const long long plane   = HW;
    const long long mstride = 3 * plane;
    const float* base  = coords + (long long)n * M * mstride + pix;
    const float* lastp = base + (long long)(M - 1) * mstride;

    float sx[TOPK], sy[TOPK];
#pragma unroll
    for (int k = 0; k < TOPK; k++) { sx[k] = 1e9f; sy[k] = 1e9f; }
    uint64_t si64 = 0;                    // 8 kept indices, byte-packed (M<256)

    // Peel m = 0: always kept (sentinel slots, cnt==0); index byte stays 0.
    {
        const float cx = base[0];
        const float cy = base[plane];
        const float cz = base[2 * plane];
        PROJECT(cx, cy, cz, sx[0], sy[0]);
    }
    int cnt = 1;

    // Pipeline prime: coords(1) projected into (x1,y1); coords(2) in regs.
    const float* s1 = (base + mstride)     < lastp ? (base + mstride)     : lastp;
    const float* s2 = (base + 2 * mstride) < lastp ? (base + 2 * mstride) : lastp;
    float x1, y1;
    {
        const float cx = s1[0], cy = s1[plane], cz = s1[2 * plane];
        PROJECT(cx, cy, cz, x1, y1);
    }
    float cx1 = s2[0], cy1 = s2[plane], cz1 = s2[2 * plane];
    const float* pf = base + 3 * mstride;

    // Vote-free warm-up: cnt cannot reach 8 before m = 7.
    int m = 1;
    const int mchk = (M < TOPK) ? M : TOPK;
    for (; m < mchk; m++) { CAND_BODY(m); }
    // Checked region: early-exit once every lane has kept 8.
    for (; m < M; m++) {
        CAND_BODY(m);
        if (__all_sync(0xffffffffu, cnt >= TOPK)) break;
    }

    // Unpack byte-packed indices to floats.
    const uint32_t lo = (uint32_t)si64;
    const uint32_t hi = (uint32_t)(si64 >> 32);
    const float f0 = (float)( lo        & 0xff);
    const float f1 = (float)((lo >>  8) & 0xff);
    const float f2 = (float)((lo >> 16) & 0xff);
    const float f3 = (float)((lo >> 24)       );
    const float f4 = (float)( hi        & 0xff);
    const float f5 = (float)((hi >>  8) & 0xff);
    const float f6 = (float)((hi >> 16) & 0xff);
    const float f7 = (float)((hi >> 24)       );

    const long long opix = (long long)n * HW + pix;
    if (VEC_STORE) {
        float4* o = reinterpret_cast<float4*>(out) + opix * 2;
        o[0] = make_float4(f0, f1, f2, f3);
        o[1] = make_float4(f4, f5, f6, f7);
    } else {
        float* o = out + opix * TOPK;
        o[0]=f0; o[1]=f1; o[2]=f2; o[3]=f3; o[4]=f4; o[5]=f5; o[6]=f6; o[7]=f7;
    }
}

// Generic fallback (any M, any HW alignment): simple, correct.
__global__ __launch_bounds__(256)
void nms_coords_kernel_generic(const float* __restrict__ coords,
                               const float* __restrict__ P,
                               float* __restrict__ out,
                               int HW, int M, int total)
{
    const int tid = blockIdx.x * 256 + threadIdx.x;
    if (tid >= total) return;
    const int n   = tid / HW;
    const int pix = tid - n * HW;
    const float* Pn = P + n * 12;
    const float p00 = Pn[0], p01 = Pn[1], p02 = Pn[2],  p03 = Pn[3];
    const float p10 = Pn[4], p11 = Pn[5], p12 = Pn[6],  p13 = Pn[7];
    const float p20 = Pn[8], p21 = Pn[9], p22 = Pn[10], p23 = Pn[11];
    const long long plane = HW, mstride = 3 * plane;
    const float* cm = coords + (long long)n * M * mstride + pix;

    float sx[TOPK], sy[TOPK]; int si[TOPK];
#pragma unroll
    for (int k = 0; k < TOPK; k++) { sx[k] = 1e9f; sy[k] = 1e9f; si[k] = 0; }
    int cnt = 0;
    for (int m = 0; m < M; m++, cm += mstride) {
        const float cx = cm[0], cy = cm[plane], cz = cm[2 * plane];
        const float X0 = fmaf(p00, cx, fmaf(p01, cy, fmaf(p02, cz, p03)));
        const float X1 = fmaf(p10, cx, fmaf(p11, cy, fmaf(p12, cz, p13)));
        const float X2 = fmaf(p20, cx, fmaf(p21, cy, fmaf(p22, cz, p23)));
        const float zc = fmaxf(X2, 1e-6f);
        const float x = X0 / zc, y = X1 / zc;
        float dmin = 3.402823e38f;
#pragma unroll
        for (int k = 0; k < TOPK; k++) {
            const float dx = sx[k] - x, dy = sy[k] - y;
            dmin = fminf(dmin, fmaf(dx, dx, dy * dy));
        }
        if (dmin > 4.0f && cnt < TOPK) {
#pragma unroll
            for (int k = 0; k < TOPK; k++)
                if (cnt == k) { sx[k] = x; sy[k] = y; si[k] = m; }
            cnt++;
        }
    }
    float* o = out + (long long)tid * TOPK;
#pragma unroll
    for (int k = 0; k < TOPK; k++) o[k] = (float)si[k];
}

extern "C" void kernel_launch(void* const* d_in, const int* in_sizes, int n_in,
                              void* d_out, int out_size)
{
    int ci = 0, pi = 0;
    for (int i = 1; i < n_in; i++) {
        if (in_sizes[i] > in_sizes[ci]) ci = i;
        if (in_sizes[i] < in_sizes[pi]) pi = i;
    }
    const float* coords = (const float*)d_in[ci];
    const float* P      = (const float*)d_in[pi];
    float* out          = (float*)d_out;

    const long long p_elems      = in_sizes[pi];
    const long long coords_elems = in_sizes[ci];
    const int N  = (int)(p_elems / 12);
    const int HW = (int)(out_size / (TOPK * (long long)N));
    const int M  = (int)(coords_elems / (3LL * N * HW));
    const int total = N * HW;

    const bool fast = (HW % 256 == 0) && (M >= 2) && (M <= 255);
    if (fast) {
        const int blocks = total / 256;            // exact
        if ((((uintptr_t)d_out) & 15u) == 0)
            nms_coords_kernel<true><<<blocks, 256>>>(coords, P, out, HW, M);
        else
            nms_coords_kernel<false><<<blocks, 256>>>(coords, P, out, HW, M);
    } else {
        const int blocks = (total + 255) / 256;
        nms_coords_kernel_generic<<<blocks, 256>>>(coords, P, out, HW, M, total);
    }
}